// round 10
// baseline (speedup 1.0000x reference)
#include <cuda_runtime.h>
#include <stdint.h>

// YOLO loss, persistent pipelined kernel, fully prefetched:
//   pred+tcls staged via cp.async double buffer (1 commit group per tile),
//   tbox+mask prefetched one tile ahead in registers. Zero exposed latency.
// Output: 5 f32 [total, reg, contain, noobj, cls] / N.

#define SGRID 28
#define TPB   96
#define WPB   (TPB / 32)
#define L_COORD 5.0
#define L_NOOBJ 0.5

__device__ double       g_acc[4] = {0.0, 0.0, 0.0, 0.0};  // cls, noobj, reg, contain
__device__ unsigned int g_count  = 0;

__device__ __forceinline__ void cp16(uint32_t dst, const void* src) {
    asm volatile("cp.async.cg.shared.global [%0], [%1], 16;" :: "r"(dst), "l"(src));
}

__device__ __forceinline__ float iou_vs_t(float bcx, float bcy, float bw, float bh,
                                          float t0, float t1, float t2, float t3) {
    const float invS = 1.0f / (float)SGRID;
    float bx = bcx * invS, by = bcy * invS;
    float b0 = bx - 0.5f * bw, b1 = by - 0.5f * bh;
    float b2 = bx + 0.5f * bw, b3 = by + 0.5f * bh;
    float lt0 = fmaxf(b0, t0), lt1 = fmaxf(b1, t1);
    float rb0 = fminf(b2, t2), rb1 = fminf(b3, t3);
    float w = fmaxf(rb0 - lt0, 0.0f), h = fmaxf(rb1 - lt1, 0.0f);
    float inter = w * h;
    float a1 = (b2 - b0) * (b3 - b1);
    float a2 = (t2 - t0) * (t3 - t1);
    float denom = a1 + a2 - inter;
    return inter / (denom > 0.0f ? denom : 1.0f);
}

// per-warp buffer: [pred 960 f][tcls 640 f] x2  = 3200 floats = 12.8 KB
#define WBUF 3200

__global__ void __launch_bounds__(TPB)
yolo_fused(const float* __restrict__ pred,
           const float* __restrict__ tbox,
           const float* __restrict__ tcls,
           const void*  __restrict__ mask,
           int ncells, int ntiles,
           float* __restrict__ out, double invN) {
    __shared__ float  s_buf[WPB * WBUF];
    __shared__ float4 s_red[WPB];
    __shared__ int    s_last;

    const int tid = threadIdx.x;
    const int lid = tid & 31;
    const int wid = tid >> 5;

    if (tid == 0) s_last = 0;

    // ---- mask dtype detection: per-warp, 512B L2-hot, pure bit ops ----
    // f32 1.0 has bytes >1; int32 0/1 has nonzero bytes only at off%4==0.
    bool four_byte;
    {
        uint4 v = ((const uint4*)mask)[lid];           // mask buffer >= 784 B
        unsigned int a = v.x | v.y | v.z | v.w;
        int gt1 = __any_sync(0xFFFFFFFFu, (a & 0xFEFEFEFEu) != 0u);
        int off = __any_sync(0xFFFFFFFFu, (a & 0xFFFFFF00u) != 0u);
        four_byte = (gt1 != 0) || (off == 0);
    }

    float* wbase_s = s_buf + wid * WBUF;
    float* pbuf[2] = { wbase_s,        wbase_s + 1600 };
    float* cbuf[2] = { wbase_s + 960,  wbase_s + 1600 + 960 };
    uint32_t psb[2] = { (uint32_t)__cvta_generic_to_shared(pbuf[0]),
                        (uint32_t)__cvta_generic_to_shared(pbuf[1]) };
    uint32_t csb[2] = { (uint32_t)__cvta_generic_to_shared(cbuf[0]),
                        (uint32_t)__cvta_generic_to_shared(cbuf[1]) };

    const int W = gridDim.x * WPB;                 // total warps in grid
    const int wstart = blockIdx.x * WPB + wid;

    // stage pred+tcls for tile t into buffer b (one commit group)
    auto stage = [&](int t, int b) {
        int base = t * 32;
        int wcnt = min(32, ncells - base);
        if (wcnt == 32) {
            const uint4* gp = (const uint4*)(pred + (size_t)base * 30);
            #pragma unroll
            for (int k = 0; k < 7; k++)
                cp16(psb[b] + (uint32_t)(lid + k * 32) * 16u, gp + lid + k * 32);
            if (lid < 16)
                cp16(psb[b] + (uint32_t)(224 + lid) * 16u, gp + 224 + lid);
            const uint4* gc = (const uint4*)(tcls + (size_t)base * 20);
            #pragma unroll
            for (int k = 0; k < 5; k++)
                cp16(csb[b] + (uint32_t)(lid + k * 32) * 16u, gc + lid + k * 32);
        } else {
            for (int e = lid; e < wcnt * 30; e += 32)
                pbuf[b][e] = pred[(size_t)base * 30 + e];
            for (int e = lid; e < wcnt * 20; e += 32)
                cbuf[b][e] = tcls[(size_t)base * 20 + e];
        }
        asm volatile("cp.async.commit_group;");
    };
    // register prefetch of tbox + mask for tile t
    auto pfetch = [&](int t, float4& ptb, float& pfm) {
        int c = t * 32 + lid;
        if (c < ncells) {
            ptb = __ldg((const float4*)tbox + c);
            if (four_byte) pfm = (((const unsigned int*)mask)[c] != 0u) ? 1.0f : 0.0f;
            else           pfm = (((const unsigned char*)mask)[c] != 0)  ? 1.0f : 0.0f;
        }
    };

    float acls = 0.0f, ano = 0.0f, areg = 0.0f, act = 0.0f;

    float4 pf_tb = make_float4(0.f, 0.f, 0.f, 0.f);
    float  pf_fm = 0.0f;

    int t = wstart;
    int buf = 0;
    if (t < ntiles) { stage(t, 0); pfetch(t, pf_tb, pf_fm); }

    for (; t < ntiles; t += W) {
        int nxt = t + W;
        if (nxt < ntiles) {
            stage(nxt, buf ^ 1);
            asm volatile("cp.async.wait_group 1;" ::: "memory");
        } else {
            asm volatile("cp.async.wait_group 0;" ::: "memory");
        }
        __syncwarp();

        float4 tb = pf_tb;
        float  fm = pf_fm;
        if (nxt < ntiles) pfetch(nxt, pf_tb, pf_fm);   // overlaps compute below

        const float* sp = pbuf[buf];
        const float* sc = cbuf[buf];
        const int base = t * 32;
        const int wcnt = min(32, ncells - base);

        if (lid < wcnt) {
            const float2* P2 = (const float2*)(sp + lid * 30);
            const float4* C4 = (const float4*)(sc + lid * 20);

            float2 p01 = P2[0], p23 = P2[1], p45 = P2[2], p67 = P2[3], p89 = P2[4];

            float cls = 0.0f;
            #pragma unroll
            for (int k = 0; k < 5; k++) {
                float4 cc = C4[k];
                float2 qa = P2[5 + 2 * k];
                float2 qb = P2[6 + 2 * k];
                float d0 = qa.x - cc.x, d1 = qa.y - cc.y;
                float d2 = qb.x - cc.z, d3 = qb.y - cc.w;
                cls = fmaf(d0, d0, cls);
                cls = fmaf(d1, d1, cls);
                cls = fmaf(d2, d2, cls);
                cls = fmaf(d3, d3, cls);
            }
            acls += fm * cls;

            ano += (1.0f - fm) * (p45.x * p45.x + p89.y * p89.y);  // raw; x0.5 at end

            const float invS = 1.0f / (float)SGRID;
            float tx = tb.x * invS, ty = tb.y * invS;
            float t0 = tx - 0.5f * tb.z, t1 = ty - 0.5f * tb.w;
            float t2 = tx + 0.5f * tb.z, t3 = ty + 0.5f * tb.w;

            // box1=(p01.x,p01.y,p23.x,p23.y,p45.x) box2=(p45.y,p67.x,p67.y,p89.x,p89.y)
            float i1 = iou_vs_t(p01.x, p01.y, p23.x, p23.y, t0, t1, t2, t3);
            float i2 = iou_vs_t(p45.y, p67.x, p67.y, p89.x, t0, t1, t2, t3);
            bool take1 = i1 > i2;
            float bx0 = take1 ? p01.x : p45.y;
            float bx1 = take1 ? p01.y : p67.x;
            float bx2 = take1 ? p23.x : p67.y;
            float bx3 = take1 ? p23.y : p89.x;
            float bx4 = take1 ? p45.x : p89.y;
            float best_iou = take1 ? i1 : i2;

            float dx = bx0 - tb.x, dy = bx1 - tb.y;
            float xy = dx * dx + dy * dy;

            bool on = fm > 0.0f;
            float dw = sqrtf(on ? bx2 : 1.0f) - sqrtf(on ? tb.z : 1.0f);
            float dh = sqrtf(on ? bx3 : 1.0f) - sqrtf(on ? tb.w : 1.0f);
            areg += fm * (xy + dw * dw + dh * dh);                 // raw; x5 at end

            float dc = bx4 - best_iou;
            act += fm * dc * dc;
        }
        __syncwarp();      // all lanes done with buf before it is restaged
        buf ^= 1;
    }

    // ---- reduce: warp shuffles -> smem -> fp64 atomics ----
    #pragma unroll
    for (int o = 16; o > 0; o >>= 1) {
        acls += __shfl_down_sync(0xFFFFFFFFu, acls, o);
        ano  += __shfl_down_sync(0xFFFFFFFFu, ano,  o);
        areg += __shfl_down_sync(0xFFFFFFFFu, areg, o);
        act  += __shfl_down_sync(0xFFFFFFFFu, act,  o);
    }
    if (lid == 0) s_red[wid] = make_float4(acls, ano, areg, act);
    __syncthreads();
    if (tid == 0) {
        float4 v = s_red[0];
        #pragma unroll
        for (int w = 1; w < WPB; w++) {
            v.x += s_red[w].x; v.y += s_red[w].y;
            v.z += s_red[w].z; v.w += s_red[w].w;
        }
        atomicAdd(&g_acc[0], (double)v.x);
        atomicAdd(&g_acc[1], (double)v.y);
        atomicAdd(&g_acc[2], (double)v.z);
        atomicAdd(&g_acc[3], (double)v.w);
        __threadfence();
        unsigned int done = atomicAdd(&g_count, 1u);
        if (done == gridDim.x - 1u) s_last = 1;
    }
    __syncthreads();

    // ---- last block finalizes and resets for next graph replay ----
    if (s_last && tid == 0) {
        double cls = g_acc[0];
        double no  = L_NOOBJ * g_acc[1];
        double reg = L_COORD * g_acc[2];
        double ct  = g_acc[3];
        double tot = cls + no + reg + ct;
        out[0] = (float)(tot * invN);
        out[1] = (float)(reg * invN);
        out[2] = (float)(ct  * invN);
        out[3] = (float)(no  * invN);
        out[4] = (float)(cls * invN);
        g_acc[0] = 0.0; g_acc[1] = 0.0; g_acc[2] = 0.0; g_acc[3] = 0.0;
        g_count = 0;
    }
}

extern "C" void kernel_launch(void* const* d_in, const int* in_sizes, int n_in,
                              void* d_out, int out_size) {
    const float* pred = (const float*)d_in[0];
    const float* tbox = (const float*)d_in[1];
    const float* tcls = (const float*)d_in[2];
    const void*  mask = d_in[3];

    int ncells = in_sizes[0] / 30;               // N*28*28
    int nbatch = ncells / (SGRID * SGRID);       // N
    double invN = 1.0 / (double)nbatch;
    int ntiles = (ncells + 31) / 32;             // 25088 for N=1024

    int nblocks = 148 * 5;                       // one full wave at 5 blocks/SM
    int maxb = (ntiles + WPB - 1) / WPB;
    if (nblocks > maxb) nblocks = maxb;

    yolo_fused<<<nblocks, TPB>>>(pred, tbox, tcls, mask, ncells, ntiles,
                                 (float*)d_out, invN);
}

// round 11
// speedup vs baseline: 1.1289x; 1.1289x over previous
#include <cuda_runtime.h>
#include <stdint.h>

// YOLO loss, persistent pipelined kernel.
// Pred staged per-warp via cp.async double-buffer; tbox+mask prefetched one
// tile ahead in registers; tcls loads PREDICATED on mask (fm==0 lanes skip
// them entirely -> ~36MB less DRAM traffic). Single-wave persistent grid.
// Output: 5 f32 [total, reg, contain, noobj, cls] / N.

#define SGRID 28
#define TPB   128
#define WPB   (TPB / 32)
#define L_COORD 5.0
#define L_NOOBJ 0.5

__device__ double       g_acc[4] = {0.0, 0.0, 0.0, 0.0};  // cls, noobj, reg, contain
__device__ unsigned int g_count  = 0;

__device__ __forceinline__ void cp16(uint32_t dst, const void* src) {
    asm volatile("cp.async.cg.shared.global [%0], [%1], 16;" :: "r"(dst), "l"(src));
}

__device__ __forceinline__ float iou_vs_t(float bcx, float bcy, float bw, float bh,
                                          float t0, float t1, float t2, float t3) {
    const float invS = 1.0f / (float)SGRID;
    float bx = bcx * invS, by = bcy * invS;
    float b0 = bx - 0.5f * bw, b1 = by - 0.5f * bh;
    float b2 = bx + 0.5f * bw, b3 = by + 0.5f * bh;
    float lt0 = fmaxf(b0, t0), lt1 = fmaxf(b1, t1);
    float rb0 = fminf(b2, t2), rb1 = fminf(b3, t3);
    float w = fmaxf(rb0 - lt0, 0.0f), h = fmaxf(rb1 - lt1, 0.0f);
    float inter = w * h;
    float a1 = (b2 - b0) * (b3 - b1);
    float a2 = (t2 - t0) * (t3 - t1);
    float denom = a1 + a2 - inter;
    return inter / (denom > 0.0f ? denom : 1.0f);
}

__global__ void __launch_bounds__(TPB)
yolo_fused(const float* __restrict__ pred,
           const float* __restrict__ tbox,
           const float* __restrict__ tcls,
           const void*  __restrict__ mask,
           int ncells, int ntiles,
           float* __restrict__ out, double invN) {
    __shared__ float  s_pred[WPB * 2 * 960];   // 2 x 32 cells x 30 floats / warp
    __shared__ float4 s_red[WPB];
    __shared__ int    s_last;

    const int tid = threadIdx.x;
    const int lid = tid & 31;
    const int wid = tid >> 5;

    if (tid == 0) s_last = 0;

    // ---- mask dtype detection: per-warp, 512B L2-hot, pure bit ops ----
    // f32 1.0 has bytes >1; int32 0/1 has nonzero bytes only at off%4==0.
    bool four_byte;
    {
        uint4 v = ((const uint4*)mask)[lid];           // mask buffer >= 784 B
        unsigned int a = v.x | v.y | v.z | v.w;
        int gt1 = __any_sync(0xFFFFFFFFu, (a & 0xFEFEFEFEu) != 0u);
        int off = __any_sync(0xFFFFFFFFu, (a & 0xFFFFFF00u) != 0u);
        four_byte = (gt1 != 0) || (off == 0);
    }

    float* buf0 = s_pred + wid * 1920;
    float* buf1 = buf0 + 960;
    uint32_t sb0 = (uint32_t)__cvta_generic_to_shared(buf0);
    uint32_t sb1 = (uint32_t)__cvta_generic_to_shared(buf1);

    const int W = gridDim.x * WPB;                 // total warps in grid
    const int wstart = blockIdx.x * WPB + wid;

    // stage pred for tile t (one commit group)
    auto stage = [&](int t, uint32_t sb, float* sf) {
        int base = t * 32;
        int wcnt = min(32, ncells - base);
        if (wcnt == 32) {
            const uint4* gp = (const uint4*)(pred + (size_t)base * 30);
            #pragma unroll
            for (int k = 0; k < 7; k++)
                cp16(sb + (uint32_t)(lid + k * 32) * 16u, gp + lid + k * 32);
            if (lid < 16)
                cp16(sb + (uint32_t)(224 + lid) * 16u, gp + 224 + lid);
        } else {
            for (int e = lid; e < wcnt * 30; e += 32)
                sf[e] = pred[(size_t)base * 30 + e];
        }
        asm volatile("cp.async.commit_group;");
    };
    // register prefetch of tbox + mask for tile t
    auto pfetch = [&](int t, float4& ptb, float& pfm) {
        int c = t * 32 + lid;
        if (c < ncells) {
            ptb = __ldg((const float4*)tbox + c);
            if (four_byte) pfm = (((const unsigned int*)mask)[c] != 0u) ? 1.0f : 0.0f;
            else           pfm = (((const unsigned char*)mask)[c] != 0)  ? 1.0f : 0.0f;
        }
    };

    float acls = 0.0f, ano = 0.0f, areg = 0.0f, act = 0.0f;

    float4 pf_tb = make_float4(0.f, 0.f, 0.f, 0.f);
    float  pf_fm = 0.0f;

    int t = wstart;
    int buf = 0;
    if (t < ntiles) { stage(t, sb0, buf0); pfetch(t, pf_tb, pf_fm); }

    for (; t < ntiles; t += W) {
        int nxt = t + W;
        if (nxt < ntiles) {
            stage(nxt, buf ? sb0 : sb1, buf ? buf0 : buf1);
            asm volatile("cp.async.wait_group 1;" ::: "memory");
        } else {
            asm volatile("cp.async.wait_group 0;" ::: "memory");
        }
        __syncwarp();

        float4 tb = pf_tb;
        float  fm = pf_fm;
        if (nxt < ntiles) pfetch(nxt, pf_tb, pf_fm);   // overlaps compute

        const float* sp = buf ? buf1 : buf0;
        const int base = t * 32;
        const int wcnt = min(32, ncells - base);

        if (lid < wcnt) {
            const int c = base + lid;
            const float2* P2 = (const float2*)(sp + lid * 30);

            float2 p01 = P2[0], p23 = P2[1], p45 = P2[2], p67 = P2[3], p89 = P2[4];

            // classification loss — tcls only touched when fm > 0 (70% skipped)
            if (fm > 0.0f) {
                const float4* C4 = (const float4*)(tcls + (size_t)c * 20);
                float cls = 0.0f;
                #pragma unroll
                for (int k = 0; k < 5; k++) {
                    float4 cc = __ldg(C4 + k);
                    float2 qa = P2[5 + 2 * k];
                    float2 qb = P2[6 + 2 * k];
                    float d0 = qa.x - cc.x, d1 = qa.y - cc.y;
                    float d2 = qb.x - cc.z, d3 = qb.y - cc.w;
                    cls = fmaf(d0, d0, cls);
                    cls = fmaf(d1, d1, cls);
                    cls = fmaf(d2, d2, cls);
                    cls = fmaf(d3, d3, cls);
                }
                acls += cls;                            // fm==1 here
            }

            ano += (1.0f - fm) * (p45.x * p45.x + p89.y * p89.y);  // raw; x0.5 at end

            const float invS = 1.0f / (float)SGRID;
            float tx = tb.x * invS, ty = tb.y * invS;
            float t0 = tx - 0.5f * tb.z, t1 = ty - 0.5f * tb.w;
            float t2 = tx + 0.5f * tb.z, t3 = ty + 0.5f * tb.w;

            // box1=(p01.x,p01.y,p23.x,p23.y,p45.x) box2=(p45.y,p67.x,p67.y,p89.x,p89.y)
            float i1 = iou_vs_t(p01.x, p01.y, p23.x, p23.y, t0, t1, t2, t3);
            float i2 = iou_vs_t(p45.y, p67.x, p67.y, p89.x, t0, t1, t2, t3);
            bool take1 = i1 > i2;
            float bx0 = take1 ? p01.x : p45.y;
            float bx1 = take1 ? p01.y : p67.x;
            float bx2 = take1 ? p23.x : p67.y;
            float bx3 = take1 ? p23.y : p89.x;
            float bx4 = take1 ? p45.x : p89.y;
            float best_iou = take1 ? i1 : i2;

            float dx = bx0 - tb.x, dy = bx1 - tb.y;
            float xy = dx * dx + dy * dy;

            bool on = fm > 0.0f;
            float dw = sqrtf(on ? bx2 : 1.0f) - sqrtf(on ? tb.z : 1.0f);
            float dh = sqrtf(on ? bx3 : 1.0f) - sqrtf(on ? tb.w : 1.0f);
            areg += fm * (xy + dw * dw + dh * dh);                 // raw; x5 at end

            float dc = bx4 - best_iou;
            act += fm * dc * dc;
        }
        __syncwarp();      // all lanes done with buf before restage
        buf ^= 1;
    }

    // ---- reduce: warp shuffles -> smem -> fp64 atomics ----
    #pragma unroll
    for (int o = 16; o > 0; o >>= 1) {
        acls += __shfl_down_sync(0xFFFFFFFFu, acls, o);
        ano  += __shfl_down_sync(0xFFFFFFFFu, ano,  o);
        areg += __shfl_down_sync(0xFFFFFFFFu, areg, o);
        act  += __shfl_down_sync(0xFFFFFFFFu, act,  o);
    }
    if (lid == 0) s_red[wid] = make_float4(acls, ano, areg, act);
    __syncthreads();
    if (tid == 0) {
        float4 v = s_red[0];
        #pragma unroll
        for (int w = 1; w < WPB; w++) {
            v.x += s_red[w].x; v.y += s_red[w].y;
            v.z += s_red[w].z; v.w += s_red[w].w;
        }
        atomicAdd(&g_acc[0], (double)v.x);
        atomicAdd(&g_acc[1], (double)v.y);
        atomicAdd(&g_acc[2], (double)v.z);
        atomicAdd(&g_acc[3], (double)v.w);
        __threadfence();
        unsigned int done = atomicAdd(&g_count, 1u);
        if (done == gridDim.x - 1u) s_last = 1;
    }
    __syncthreads();

    // ---- last block finalizes and resets for next graph replay ----
    if (s_last && tid == 0) {
        double cls = g_acc[0];
        double no  = L_NOOBJ * g_acc[1];
        double reg = L_COORD * g_acc[2];
        double ct  = g_acc[3];
        double tot = cls + no + reg + ct;
        out[0] = (float)(tot * invN);
        out[1] = (float)(reg * invN);
        out[2] = (float)(ct  * invN);
        out[3] = (float)(no  * invN);
        out[4] = (float)(cls * invN);
        g_acc[0] = 0.0; g_acc[1] = 0.0; g_acc[2] = 0.0; g_acc[3] = 0.0;
        g_count = 0;
    }
}

extern "C" void kernel_launch(void* const* d_in, const int* in_sizes, int n_in,
                              void* d_out, int out_size) {
    const float* pred = (const float*)d_in[0];
    const float* tbox = (const float*)d_in[1];
    const float* tcls = (const float*)d_in[2];
    const void*  mask = d_in[3];

    int ncells = in_sizes[0] / 30;               // N*28*28
    int nbatch = ncells / (SGRID * SGRID);       // N
    double invN = 1.0 / (double)nbatch;
    int ntiles = (ncells + 31) / 32;             // 25088 for N=1024

    int nblocks = 148 * 7;                       // one wave at 7 blocks/SM
    int maxb = (ntiles + WPB - 1) / WPB;
    if (nblocks > maxb) nblocks = maxb;

    yolo_fused<<<nblocks, TPB>>>(pred, tbox, tcls, mask, ncells, ntiles,
                                 (float*)d_out, invN);
}